// round 1
// baseline (speedup 1.0000x reference)
#include <cuda_runtime.h>

// Problem constants (fixed shapes for this problem instance)
#define NPTS   128          // n_points
#define STEPS  64           // velocity steps
#define NCH    4            // s-chunks per (i,j) pair in non-event part
#define TPB    256

static __device__ __constant__ float kDELTA   = (float)(100.0 / 63.0);   // fp32-rounded MAX_TIME/(STEPS-1)
static __device__ __constant__ float kEPS     = 1e-9f;
static __device__ __constant__ float kSQPI_2  = 0.8862269254527580f;     // sqrt(pi)/2

// Per-block double partial sums (overwritten fully every launch -> graph-safe)
__device__ double g_part[1024];

__device__ __forceinline__ double block_reduce_d(double v, double* sh) {
    int tid = threadIdx.x;
    #pragma unroll
    for (int off = 16; off > 0; off >>= 1)
        v += __shfl_down_sync(0xffffffffu, v, off);
    if ((tid & 31) == 0) sh[tid >> 5] = v;
    __syncthreads();
    if (tid < 8) {
        v = sh[tid];
        #pragma unroll
        for (int off = 4; off > 0; off >>= 1)
            v += __shfl_down_sync(0xffu, v, off);
    }
    return v;  // valid on tid 0
}

__global__ void __launch_bounds__(TPB)
k_main(const float* __restrict__ beta,
       const float* __restrict__ z0,
       const float* __restrict__ v0,
       const float* __restrict__ ev,
       const int*   __restrict__ pi,
       const int*   __restrict__ pj,
       int P, int E, int NB_EV)
{
    __shared__ double sred[8];
    const int tid = threadIdx.x;
    double acc = 0.0;

    if ((int)blockIdx.x < NB_EV) {
        // ---------------- event (pair) term ----------------
        __shared__ float sS1[STEPS];
        __shared__ float sS2[STEPS];
        if (tid < STEPS) { sS1[tid] = 0.f; sS2[tid] = 0.f; }
        __syncthreads();

        // Histogram of event times: S1[s] = sum a, S2[s] = sum a^2
        for (int e = tid; e < E; e += TPB) {
            float t  = ev[e];
            float tv = __fdiv_rn(t, kDELTA);   // match JAX fp32 division exactly
            float f  = floorf(tv);
            float fr = tv - f;                 // frac from UNclipped floor (matches ref)
            int   s  = (int)f;
            s = max(0, min(STEPS - 1, s));
            float a = (s == 0 ? 0.0f : kDELTA) + fr;  // td[s] + frac
            atomicAdd(&sS1[s], a);
            atomicAdd(&sS2[s], a * a);
        }
        __syncthreads();

        const int p = blockIdx.x * TPB + tid;
        if (p < P) {
            const int i = pi[p], j = pj[p];
            const float dzx = z0[2*i]   - z0[2*j];
            const float dzy = z0[2*i+1] - z0[2*j+1];
            const float* vi = v0 + (size_t)(2*i) * STEPS;
            const float* vj = v0 + (size_t)(2*j) * STEPS;
            acc = (double)E * (double)(dzx*dzx + dzy*dzy);
            #pragma unroll 8
            for (int s = 0; s < STEPS; s++) {
                float dvx = vi[s]         - vj[s];
                float dvy = vi[STEPS + s] - vj[STEPS + s];
                float B = dzx*dvx + dzy*dvy;      // dz0 . dv_s
                float C = dvx*dvx + dvy*dvy;      // |dv_s|^2
                acc += (double)(2.0f * sS1[s] * B + sS2[s] * C);
            }
        }
    } else {
        // ---------------- non-event (integral) term ----------------
        // gid -> (chunk of 16 steps, pair q = i*128 + j)
        const int gid   = (blockIdx.x - NB_EV) * TPB + tid;
        const int chunk = gid & (NCH - 1);
        const int q     = gid >> 2;
        const int i     = q >> 7;
        const int j     = q & 127;
        if (j > i) {
            const float bb   = beta[0];
            const float dzx0 = z0[2*i]   - z0[2*j];
            const float dzy0 = z0[2*i+1] - z0[2*j+1];
            const float* vi  = v0 + (size_t)(2*i) * STEPS;
            const float* vj  = v0 + (size_t)(2*j) * STEPS;
            const int s_beg = chunk * (STEPS / NCH);
            const int s_end = s_beg + (STEPS / NCH);
            // s = 0 contributes exactly 0 (time_deltas[0] == 0 -> erf diff == 0)
            for (int s = (s_beg == 0 ? 1 : s_beg); s < s_end; s++) {
                float dvx = vi[s]         - vj[s];
                float dvy = vi[STEPS + s] - vj[STEPS + s];
                float r2  = dvx*dvx + dvy*dvy + kEPS;
                float r   = sqrtf(r2);
                // Z_steps is NOT cumulative: dz(s) = dz0 + dv_s * DELTA  (s >= 1)
                float dzx = dzx0 + dvx * kDELTA;
                float dzy = dzy0 + dvy * kDELTA;
                float zdv = dzx*dvx + dzy*dvy;
                float ir2 = 1.0f / r2;
                float bsh = zdv * ir2;
                float c   = dzx*dzx + dzy*dzy - zdv*zdv*ir2;
                float val = expf(bb - c) * (kSQPI_2 / r)
                          * (erff(r * (kDELTA + bsh)) - erff(r * bsh));
                acc += (double)val;
            }
        }
    }

    double tot = block_reduce_d(acc, sred);
    if (tid == 0) g_part[blockIdx.x] = tot;
}

__global__ void __launch_bounds__(TPB)
k_final(const float* __restrict__ beta, float* __restrict__ out,
        int nblocks, double PE)
{
    __shared__ double sred[8];
    const int tid = threadIdx.x;
    double acc = 0.0;
    for (int b = tid; b < nblocks; b += TPB) acc += g_part[b];
    double tot = block_reduce_d(acc, sred);
    if (tid == 0)
        out[0] = (float)(PE * (double)beta[0] - tot);
}

extern "C" void kernel_launch(void* const* d_in, const int* in_sizes, int n_in,
                              void* d_out, int out_size)
{
    const float* beta = (const float*)d_in[0];
    const float* z0   = (const float*)d_in[1];
    const float* v0   = (const float*)d_in[2];
    const float* ev   = (const float*)d_in[3];
    // d_in[4] = t0, d_in[5] = tn : unused by the math
    const int*   pi   = (const int*)d_in[6];
    const int*   pj   = (const int*)d_in[7];

    const int E = in_sizes[3];
    const int P = in_sizes[6];

    const int NB_EV = (P + TPB - 1) / TPB;                 // 16 for P=4000
    const int NB_NE = (NPTS * NPTS * NCH) / TPB;           // 256
    const int NB    = NB_EV + NB_NE;                       // 272

    k_main<<<NB, TPB>>>(beta, z0, v0, ev, pi, pj, P, E, NB_EV);
    k_final<<<1, TPB>>>(beta, (float*)d_out, NB, (double)P * (double)E);
}